// round 10
// baseline (speedup 1.0000x reference)
#include <cuda_runtime.h>
#include <cuda_bf16.h>
#include <cstdint>
#include <math.h>

#define B_  32768
#define D_  768
#define H_  1024
#define L_  256
#define M_  32

// ---------------- helpers ----------------
__device__ __forceinline__ uint32_t smem_to_u32(const void* p) {
    uint32_t a;
    asm("{ .reg .u64 t; cvta.to.shared.u64 t, %1; cvt.u32.u64 %0, t; }" : "=r"(a) : "l"(p));
    return a;
}
__device__ __forceinline__ void cp16(uint32_t dst, const void* src) {
    asm volatile("cp.async.cg.shared.global [%0], [%1], 16;\n" :: "r"(dst), "l"(src) : "memory");
}
#define CP_COMMIT()  asm volatile("cp.async.commit_group;\n" ::: "memory")
#define CP_WAIT(n)   asm volatile("cp.async.wait_group %0;\n" :: "n"(n) : "memory")
#define LDMATRIX_X4(r0, r1, r2, r3, addr) \
    asm volatile("ldmatrix.sync.aligned.m8n8.x4.shared.b16 {%0,%1,%2,%3}, [%4];" \
                 : "=r"(r0), "=r"(r1), "=r"(r2), "=r"(r3) : "r"(addr))
#define MMA_BF16(d, a, b0, b1) \
    asm volatile("mma.sync.aligned.m16n8k16.row.col.f32.bf16.bf16.f32 " \
                 "{%0,%1,%2,%3}, {%4,%5,%6,%7}, {%8,%9}, {%0,%1,%2,%3};" \
                 : "+f"((d)[0]), "+f"((d)[1]), "+f"((d)[2]), "+f"((d)[3]) \
                 : "r"((a)[0]), "r"((a)[1]), "r"((a)[2]), "r"((a)[3]), "r"(b0), "r"(b1))

// ---------------- scratch ----------------
#define WTOT 7340032
#define PMAX ((size_t)B_ * 2 * H_)
__device__ __nv_bfloat16 g_wh[WTOT], g_wl[WTOT];
__device__ __nv_bfloat16 g_p1h[PMAX], g_p1l[PMAX], g_p2h[PMAX], g_p2l[PMAX];
__device__ float g_f32[PMAX];
__device__ float g_bias512[512];

__device__ __forceinline__ void split2(float v, __nv_bfloat16& h, __nv_bfloat16& l) {
    h = __float2bfloat16(v);
    l = __float2bfloat16(v - __bfloat162float(h));
}

// ---------------- fp32 -> (hi,lo) bf16 split ----------------
__global__ __launch_bounds__(256)
void split_kernel(const float* __restrict__ src, __nv_bfloat16* __restrict__ hi,
                  __nv_bfloat16* __restrict__ lo, int n4) {
    int i = blockIdx.x * 256 + threadIdx.x;
    if (i >= n4) return;
    float4 v = ((const float4*)src)[i];
    __nv_bfloat16 h0, l0, h1, l1, h2, l2, h3, l3;
    split2(v.x, h0, l0); split2(v.y, h1, l1); split2(v.z, h2, l2); split2(v.w, h3, l3);
    ((__nv_bfloat162*)hi)[i * 2]     = __halves2bfloat162(h0, h1);
    ((__nv_bfloat162*)hi)[i * 2 + 1] = __halves2bfloat162(h2, h3);
    ((__nv_bfloat162*)lo)[i * 2]     = __halves2bfloat162(l0, l1);
    ((__nv_bfloat162*)lo)[i * 2 + 1] = __halves2bfloat162(l2, l3);
}

// ---------------- split-bf16 GEMM via mma.sync (HMMA) ----------------
// C[B,N] = A[B,K] @ W[N,K]^T + bias; acc += Ah*Wh + Ah*Wl + Al*Wh (fp32 acc).
// CTA 128x256, BK=32, 256 threads, warp tile 64x64 (warps 2m x 4n).
// 3-stage cp.async pipeline; product-major MMA ordering (no RAW chains).
#define ARR_A   10240           // 128 * 80
#define ARR_W   20480           // 256 * 80
#define AW_OFF  (2 * ARR_A)
#define STAGE_B (2 * ARR_A + 2 * ARR_W)   // 61440
#define NSTAGE  3
#define GSMEM   (NSTAGE * STAGE_B)        // 184320

template<int OUT_MODE>
__global__ void __launch_bounds__(256, 1)
mma_gemm_kernel(const __nv_bfloat16* __restrict__ Ah, const __nv_bfloat16* __restrict__ Al,
                const __nv_bfloat16* __restrict__ Wh, const __nv_bfloat16* __restrict__ Wl,
                const float* __restrict__ bias, float* __restrict__ Cf,
                __nv_bfloat16* __restrict__ Oh, __nv_bfloat16* __restrict__ Ol,
                int N, int K) {
    extern __shared__ char smem[];
    const uint32_t smem_u = smem_to_u32(smem);
    const int tid  = threadIdx.x;
    const int wid  = tid >> 5, lane = tid & 31;
    const int rowBase = blockIdx.y * 128;
    const int colBase = blockIdx.x * 256;
    const int warpM = wid & 1;      // 0..1  -> 64 rows
    const int warpN = wid >> 1;     // 0..3  -> 64 cols

    float acc[4][8][4];
    #pragma unroll
    for (int t = 0; t < 4; t++)
        #pragma unroll
        for (int f = 0; f < 8; f++)
            #pragma unroll
            for (int e = 0; e < 4; e++) acc[t][f][e] = 0.f;

    uint32_t aoff[4];
    #pragma unroll
    for (int t = 0; t < 4; t++)
        aoff[t] = (uint32_t)((warpM * 64 + t * 16 + (lane & 15)) * 80 + ((lane >> 4) << 4));
    uint32_t boff[4];
    #pragma unroll
    for (int g = 0; g < 4; g++) {
        int n = warpN * 64 + g * 16 + (lane & 7) + ((lane & 16) ? 8 : 0);
        boff[g] = (uint32_t)(AW_OFF + n * 80 + ((lane & 8) ? 16 : 0));
    }

    const int ktiles = K >> 5;

    auto fill = [&](int kt) {
        const uint32_t stb = smem_u + (kt % NSTAGE) * STAGE_B;
        const int kOff = kt * 32;
        #pragma unroll
        for (int it = 0; it < 4; it++) {          // A chunks
            int idx = it * 256 + tid;
            int arr = idx >> 9;
            int r   = (idx >> 2) & 127;
            int c   = idx & 3;
            const __nv_bfloat16* src =
                (arr ? Al : Ah) + (size_t)(rowBase + r) * K + kOff + c * 8;
            cp16(stb + arr * ARR_A + r * 80 + c * 16, src);
        }
        #pragma unroll
        for (int it = 0; it < 8; it++) {          // W chunks
            int idx = it * 256 + tid;
            int arr = idx >> 10;
            int r   = (idx >> 2) & 255;
            int c   = idx & 3;
            const __nv_bfloat16* src =
                (arr ? Wl : Wh) + (size_t)(colBase + r) * K + kOff + c * 8;
            cp16(stb + AW_OFF + arr * ARR_W + r * 80 + c * 16, src);
        }
        CP_COMMIT();
    };

    fill(0);
    if (ktiles > 1) fill(1);

    for (int kt = 0; kt < ktiles; kt++) {
        if (kt + 1 < ktiles) CP_WAIT(1); else CP_WAIT(0);
        __syncthreads();
        if (kt + 2 < ktiles) fill(kt + 2);

        const uint32_t stb = smem_u + (kt % NSTAGE) * STAGE_B;
        #pragma unroll
        for (int kc = 0; kc < 2; kc++) {
            const uint32_t kb = kc * 32;
            // load all fragments for this k-chunk
            uint32_t ah[4][4], al[4][4], bh[4][4], bl[4][4];
            #pragma unroll
            for (int t = 0; t < 4; t++) {
                LDMATRIX_X4(ah[t][0], ah[t][1], ah[t][2], ah[t][3], stb + aoff[t] + kb);
                LDMATRIX_X4(al[t][0], al[t][1], al[t][2], al[t][3], stb + aoff[t] + ARR_A + kb);
            }
            #pragma unroll
            for (int g = 0; g < 4; g++) {
                LDMATRIX_X4(bh[g][0], bh[g][1], bh[g][2], bh[g][3], stb + boff[g] + kb);
                LDMATRIX_X4(bl[g][0], bl[g][1], bl[g][2], bl[g][3], stb + boff[g] + ARR_W + kb);
            }
            // product-major passes: every MMA within a pass hits a distinct acc
            #pragma unroll
            for (int t = 0; t < 4; t++)
                #pragma unroll
                for (int g = 0; g < 4; g++) {
                    MMA_BF16(acc[t][2 * g],     ah[t], bh[g][0], bh[g][1]);
                    MMA_BF16(acc[t][2 * g + 1], ah[t], bh[g][2], bh[g][3]);
                }
            #pragma unroll
            for (int t = 0; t < 4; t++)
                #pragma unroll
                for (int g = 0; g < 4; g++) {
                    MMA_BF16(acc[t][2 * g],     ah[t], bl[g][0], bl[g][1]);
                    MMA_BF16(acc[t][2 * g + 1], ah[t], bl[g][2], bl[g][3]);
                }
            #pragma unroll
            for (int t = 0; t < 4; t++)
                #pragma unroll
                for (int g = 0; g < 4; g++) {
                    MMA_BF16(acc[t][2 * g],     al[t], bh[g][0], bh[g][1]);
                    MMA_BF16(acc[t][2 * g + 1], al[t], bh[g][2], bh[g][3]);
                }
        }
        __syncthreads();
    }

    // epilogue
    const int mBase = rowBase + warpM * 64;
    const int nBase = colBase + warpN * 64;
    #pragma unroll
    for (int t = 0; t < 4; t++) {
        #pragma unroll
        for (int f = 0; f < 8; f++) {
            const int col = nBase + f * 8 + (lane & 3) * 2;
            const int r0  = mBase + t * 16 + (lane >> 2);
            const float bv0 = __ldg(bias + col), bv1 = __ldg(bias + col + 1);
            float v00 = acc[t][f][0] + bv0, v01 = acc[t][f][1] + bv1;
            float v10 = acc[t][f][2] + bv0, v11 = acc[t][f][3] + bv1;
            if (OUT_MODE == 0) {
                *(float2*)(Cf + (size_t)r0 * N + col)       = make_float2(v00, v01);
                *(float2*)(Cf + (size_t)(r0 + 8) * N + col) = make_float2(v10, v11);
            } else {
                v00 = v00 >= 0.f ? v00 : 0.2f * v00;
                v01 = v01 >= 0.f ? v01 : 0.2f * v01;
                v10 = v10 >= 0.f ? v10 : 0.2f * v10;
                v11 = v11 >= 0.f ? v11 : 0.2f * v11;
                __nv_bfloat16 h0, l0, h1, l1;
                split2(v00, h0, l0); split2(v01, h1, l1);
                *(__nv_bfloat162*)(Oh + (size_t)r0 * N + col) = __halves2bfloat162(h0, h1);
                *(__nv_bfloat162*)(Ol + (size_t)r0 * N + col) = __halves2bfloat162(l0, l1);
                split2(v10, h0, l0); split2(v11, h1, l1);
                *(__nv_bfloat162*)(Oh + (size_t)(r0 + 8) * N + col) = __halves2bfloat162(h0, h1);
                *(__nv_bfloat162*)(Ol + (size_t)(r0 + 8) * N + col) = __halves2bfloat162(l0, l1);
            }
        }
    }
}

// ---------------- LayerNorm + lrelu -> split-bf16 ----------------
__device__ __forceinline__ float block_reduce_sum(float val, float* red) {
    const int lane = threadIdx.x & 31;
    const int w    = threadIdx.x >> 5;
    #pragma unroll
    for (int o = 16; o; o >>= 1) val += __shfl_xor_sync(0xffffffffu, val, o);
    if (lane == 0) red[w] = val;
    __syncthreads();
    float t = (lane < 8) ? red[lane] : 0.f;
    if (w == 0) {
        #pragma unroll
        for (int o = 4; o; o >>= 1) t += __shfl_xor_sync(0xffffffffu, t, o);
        if (lane == 0) red[0] = t;
    }
    __syncthreads();
    float r = red[0];
    __syncthreads();
    return r;
}

template<int NV4>
__global__ __launch_bounds__(256)
void ln_split_kernel(const float* __restrict__ X, const float* __restrict__ g,
                     const float* __restrict__ b, __nv_bfloat16* __restrict__ Oh,
                     __nv_bfloat16* __restrict__ Ol) {
    const int H = NV4 * 1024;
    const int tid = threadIdx.x;
    const float* row = X + (size_t)blockIdx.x * H;
    __shared__ float red[8];

    float4 v[NV4];
    float s = 0.f;
    #pragma unroll
    for (int q = 0; q < NV4; q++) {
        v[q] = *(const float4*)(row + (tid + 256 * q) * 4);
        s += v[q].x + v[q].y + v[q].z + v[q].w;
    }
    const float mean = block_reduce_sum(s, red) * (1.f / H);

    float ss = 0.f;
    #pragma unroll
    for (int q = 0; q < NV4; q++) {
        float dx;
        dx = v[q].x - mean; ss += dx * dx;
        dx = v[q].y - mean; ss += dx * dx;
        dx = v[q].z - mean; ss += dx * dx;
        dx = v[q].w - mean; ss += dx * dx;
    }
    const float var  = block_reduce_sum(ss, red) * (1.f / H);
    const float rstd = rsqrtf(var + 1e-5f);

    __nv_bfloat16* oh = Oh + (size_t)blockIdx.x * H;
    __nv_bfloat16* ol = Ol + (size_t)blockIdx.x * H;
    #pragma unroll
    for (int q = 0; q < NV4; q++) {
        const int col = (tid + 256 * q) * 4;
        const float4 g4 = *(const float4*)(g + col);
        const float4 b4 = *(const float4*)(b + col);
        float y0 = (v[q].x - mean) * rstd * g4.x + b4.x; y0 = y0 >= 0.f ? y0 : 0.2f * y0;
        float y1 = (v[q].y - mean) * rstd * g4.y + b4.y; y1 = y1 >= 0.f ? y1 : 0.2f * y1;
        float y2 = (v[q].z - mean) * rstd * g4.z + b4.z; y2 = y2 >= 0.f ? y2 : 0.2f * y2;
        float y3 = (v[q].w - mean) * rstd * g4.w + b4.w; y3 = y3 >= 0.f ? y3 : 0.2f * y3;
        __nv_bfloat16 h0, l0, h1, l1, h2, l2, h3, l3;
        split2(y0, h0, l0); split2(y1, h1, l1); split2(y2, h2, l2); split2(y3, h3, l3);
        *(__nv_bfloat162*)(oh + col)     = __halves2bfloat162(h0, h1);
        *(__nv_bfloat162*)(oh + col + 2) = __halves2bfloat162(h2, h3);
        *(__nv_bfloat162*)(ol + col)     = __halves2bfloat162(l0, l1);
        *(__nv_bfloat162*)(ol + col + 2) = __halves2bfloat162(l2, l3);
    }
}

// ---------------- reparam + context attention -> split-bf16 ----------------
__global__ __launch_bounds__(256)
void reparam_attn_kernel(const float* __restrict__ muv, const float* __restrict__ eps,
                         const float* __restrict__ ctx,
                         float* __restrict__ out_mu, float* __restrict__ out_lv,
                         __nv_bfloat16* __restrict__ Zh, __nv_bfloat16* __restrict__ Zl) {
    __shared__ float ctxs[M_][L_ + 1];
    __shared__ float zs[8][L_];
    __shared__ float attns[8][M_];

    const int tid = threadIdx.x;
    for (int i = tid; i < M_ * L_; i += 256)
        ctxs[i >> 8][i & 255] = ctx[i];
    __syncthreads();

    const int w    = tid >> 5;
    const int lane = tid & 31;
    const size_t row = (size_t)blockIdx.x * 8 + w;
    const float* mvrow = muv + row * 512;
    const float* eprow = eps + row * L_;

    #pragma unroll
    for (int i = 0; i < 8; i++) {
        const int j = lane + 32 * i;
        const float mu = mvrow[j], lv = mvrow[256 + j];
        out_mu[row * L_ + j] = mu;
        out_lv[row * L_ + j] = lv;
        zs[w][j] = mu + eprow[j] * expf(0.5f * lv);
    }
    __syncwarp();

    float s = 0.f;
    #pragma unroll 8
    for (int j = 0; j < L_; j++)
        s = fmaf(zs[w][j], ctxs[lane][j], s);

    float mx = s;
    #pragma unroll
    for (int o = 16; o; o >>= 1) mx = fmaxf(mx, __shfl_xor_sync(0xffffffffu, mx, o));
    float e = expf(s - mx);
    float tot = e;
    #pragma unroll
    for (int o = 16; o; o >>= 1) tot += __shfl_xor_sync(0xffffffffu, tot, o);
    attns[w][lane] = e / tot;
    __syncwarp();

    __nv_bfloat16* zh = Zh + row * L_;
    __nv_bfloat16* zl = Zl + row * L_;
    #pragma unroll
    for (int i = 0; i < 8; i++) {
        const int j = lane + 32 * i;
        float add = 0.f;
        #pragma unroll
        for (int m = 0; m < M_; m++)
            add = fmaf(attns[w][m], ctxs[m][j], add);
        float v = zs[w][j] + 0.1f * add;
        __nv_bfloat16 h, l;
        split2(v, h, l);
        zh[j] = h; zl[j] = l;
    }
}

// ---------------------------------------------------------------------------
extern "C" void kernel_launch(void* const* d_in, const int* in_sizes, int n_in,
                              void* d_out, int out_size) {
    (void)in_sizes; (void)n_in; (void)out_size;
    const float* x      = (const float*)d_in[0];
    const float* eps    = (const float*)d_in[1];
    const float* enc_w1 = (const float*)d_in[2];
    const float* enc_b1 = (const float*)d_in[3];
    const float* ln1_g  = (const float*)d_in[4];
    const float* ln1_b  = (const float*)d_in[5];
    const float* enc_w2 = (const float*)d_in[6];
    const float* enc_b2 = (const float*)d_in[7];
    const float* ln2_g  = (const float*)d_in[8];
    const float* ln2_b  = (const float*)d_in[9];
    const float* mu_w   = (const float*)d_in[10];
    const float* mu_b   = (const float*)d_in[11];
    const float* lv_w   = (const float*)d_in[12];
    const float* lv_b   = (const float*)d_in[13];
    const float* di_w   = (const float*)d_in[14];
    const float* di_b   = (const float*)d_in[15];
    const float* dec_w1 = (const float*)d_in[16];
    const float* dec_b1 = (const float*)d_in[17];
    const float* dln1_g = (const float*)d_in[18];
    const float* dln1_b = (const float*)d_in[19];
    const float* dec_w2 = (const float*)d_in[20];
    const float* dec_b2 = (const float*)d_in[21];
    const float* dln2_g = (const float*)d_in[22];
    const float* dln2_b = (const float*)d_in[23];
    const float* dec_w3 = (const float*)d_in[24];
    const float* dec_b3 = (const float*)d_in[25];
    const float* ctx    = (const float*)d_in[26];

    float* out     = (float*)d_out;
    float* out_rec = out;
    float* out_mu  = out + (size_t)B_ * D_;
    float* out_lv  = out_mu + (size_t)B_ * L_;

    __nv_bfloat16 *wh, *wl, *p1h, *p1l, *p2h, *p2l;
    float *f32buf, *bias512;
    cudaGetSymbolAddress((void**)&wh, g_wh);
    cudaGetSymbolAddress((void**)&wl, g_wl);
    cudaGetSymbolAddress((void**)&p1h, g_p1h);
    cudaGetSymbolAddress((void**)&p1l, g_p1l);
    cudaGetSymbolAddress((void**)&p2h, g_p2h);
    cudaGetSymbolAddress((void**)&p2l, g_p2l);
    cudaGetSymbolAddress((void**)&f32buf, g_f32);
    cudaGetSymbolAddress((void**)&bias512, g_bias512);

    cudaFuncSetAttribute(mma_gemm_kernel<0>, cudaFuncAttributeMaxDynamicSharedMemorySize, GSMEM);
    cudaFuncSetAttribute(mma_gemm_kernel<1>, cudaFuncAttributeMaxDynamicSharedMemorySize, GSMEM);

    const size_t o_e1 = 0,       o_e2 = 786432,  o_mu = 1835008, o_lv = 2097152;
    const size_t o_di = 2359296, o_d1 = 2621440, o_d2 = 3670016, o_d3 = 5767168;

    cudaMemcpyAsync(bias512,       mu_b, 256 * sizeof(float), cudaMemcpyDeviceToDevice);
    cudaMemcpyAsync(bias512 + 256, lv_b, 256 * sizeof(float), cudaMemcpyDeviceToDevice);

    const dim3 blk(256);
    auto splt = [&](const float* s, __nv_bfloat16* h, __nv_bfloat16* l, size_t n) {
        int n4 = (int)(n / 4);
        split_kernel<<<(n4 + 255) / 256, blk>>>(s, h, l, n4);
    };

    splt(x,      p1h,       p1l,       (size_t)B_ * D_);
    splt(enc_w1, wh + o_e1, wl + o_e1, (size_t)H_ * D_);
    splt(enc_w2, wh + o_e2, wl + o_e2, (size_t)H_ * H_);
    splt(mu_w,   wh + o_mu, wl + o_mu, (size_t)L_ * H_);
    splt(lv_w,   wh + o_lv, wl + o_lv, (size_t)L_ * H_);
    splt(di_w,   wh + o_di, wl + o_di, (size_t)H_ * L_);
    splt(dec_w1, wh + o_d1, wl + o_d1, (size_t)H_ * H_);
    splt(dec_w2, wh + o_d2, wl + o_d2, (size_t)2 * H_ * H_);
    splt(dec_w3, wh + o_d3, wl + o_d3, (size_t)D_ * 2 * H_);

    auto gemm = [&](int mode, const __nv_bfloat16* ah, const __nv_bfloat16* al,
                    size_t wo, const float* bias, float* cf,
                    __nv_bfloat16* oh, __nv_bfloat16* ol, int N, int K) {
        dim3 g(N / 256, B_ / 128);
        if (mode == 0)
            mma_gemm_kernel<0><<<g, blk, GSMEM>>>(ah, al, wh + wo, wl + wo, bias, cf, oh, ol, N, K);
        else
            mma_gemm_kernel<1><<<g, blk, GSMEM>>>(ah, al, wh + wo, wl + wo, bias, cf, oh, ol, N, K);
    };

    // encoder
    gemm(0, p1h, p1l, o_e1, enc_b1, f32buf, nullptr, nullptr, H_, D_);
    ln_split_kernel<1><<<B_, blk>>>(f32buf, ln1_g, ln1_b, p2h, p2l);
    gemm(0, p2h, p2l, o_e2, enc_b2, f32buf, nullptr, nullptr, H_, H_);
    ln_split_kernel<1><<<B_, blk>>>(f32buf, ln2_g, ln2_b, p1h, p1l);
    // merged mu|lv GEMM -> f32buf [B, 512]
    gemm(0, p1h, p1l, o_mu, bias512, f32buf, nullptr, nullptr, 512, H_);
    reparam_attn_kernel<<<B_ / 8, blk>>>(f32buf, eps, ctx, out_mu, out_lv, p2h, p2l);
    // decoder
    gemm(1, p2h, p2l, o_di, di_b, nullptr, p1h, p1l, H_, L_);
    gemm(0, p1h, p1l, o_d1, dec_b1, f32buf, nullptr, nullptr, H_, H_);
    ln_split_kernel<1><<<B_, blk>>>(f32buf, dln1_g, dln1_b, p2h, p2l);
    gemm(0, p2h, p2l, o_d2, dec_b2, f32buf, nullptr, nullptr, 2 * H_, H_);
    ln_split_kernel<2><<<B_, blk>>>(f32buf, dln2_g, dln2_b, p1h, p1l);
    gemm(0, p1h, p1l, o_d3, dec_b3, out_rec, nullptr, nullptr, D_, 2 * H_);
}

// round 11
// speedup vs baseline: 1.1167x; 1.1167x over previous
#include <cuda_runtime.h>
#include <cuda_bf16.h>
#include <cstdint>
#include <math.h>

#define B_  32768
#define D_  768
#define H_  1024
#define L_  256
#define M_  32

// ---------------- helpers ----------------
__device__ __forceinline__ uint32_t smem_to_u32(const void* p) {
    uint32_t a;
    asm("{ .reg .u64 t; cvta.to.shared.u64 t, %1; cvt.u32.u64 %0, t; }" : "=r"(a) : "l"(p));
    return a;
}
__device__ __forceinline__ void cp16(uint32_t dst, const void* src) {
    asm volatile("cp.async.cg.shared.global [%0], [%1], 16;\n" :: "r"(dst), "l"(src) : "memory");
}
#define CP_COMMIT()  asm volatile("cp.async.commit_group;\n" ::: "memory")
#define CP_WAIT(n)   asm volatile("cp.async.wait_group %0;\n" :: "n"(n) : "memory")
#define LDMATRIX_X4(r0, r1, r2, r3, addr) \
    asm volatile("ldmatrix.sync.aligned.m8n8.x4.shared.b16 {%0,%1,%2,%3}, [%4];" \
                 : "=r"(r0), "=r"(r1), "=r"(r2), "=r"(r3) : "r"(addr))
#define MMA_BF16(d, a, b0, b1) \
    asm volatile("mma.sync.aligned.m16n8k16.row.col.f32.bf16.bf16.f32 " \
                 "{%0,%1,%2,%3}, {%4,%5,%6,%7}, {%8,%9}, {%0,%1,%2,%3};" \
                 : "+f"((d)[0]), "+f"((d)[1]), "+f"((d)[2]), "+f"((d)[3]) \
                 : "r"((a)[0]), "r"((a)[1]), "r"((a)[2]), "r"((a)[3]), "r"(b0), "r"(b1))

// ---------------- scratch ----------------
#define WTOT 7340032
#define PMAX ((size_t)B_ * 2 * H_)
__device__ __nv_bfloat16 g_wh[WTOT], g_wl[WTOT];
__device__ __nv_bfloat16 g_p1h[PMAX], g_p1l[PMAX], g_p2h[PMAX], g_p2l[PMAX];
__device__ float g_f32[PMAX];
__device__ float g_bias512[512];

__device__ __forceinline__ void split2(float v, __nv_bfloat16& h, __nv_bfloat16& l) {
    h = __float2bfloat16(v);
    l = __float2bfloat16(v - __bfloat162float(h));
}

// ---------------- fp32 -> (hi,lo) bf16 split ----------------
__global__ __launch_bounds__(256)
void split_kernel(const float* __restrict__ src, __nv_bfloat16* __restrict__ hi,
                  __nv_bfloat16* __restrict__ lo, int n4) {
    int i = blockIdx.x * 256 + threadIdx.x;
    if (i >= n4) return;
    float4 v = ((const float4*)src)[i];
    __nv_bfloat16 h0, l0, h1, l1, h2, l2, h3, l3;
    split2(v.x, h0, l0); split2(v.y, h1, l1); split2(v.z, h2, l2); split2(v.w, h3, l3);
    ((__nv_bfloat162*)hi)[i * 2]     = __halves2bfloat162(h0, h1);
    ((__nv_bfloat162*)hi)[i * 2 + 1] = __halves2bfloat162(h2, h3);
    ((__nv_bfloat162*)lo)[i * 2]     = __halves2bfloat162(l0, l1);
    ((__nv_bfloat162*)lo)[i * 2 + 1] = __halves2bfloat162(l2, l3);
}

// ---------------- split-bf16 GEMM via mma.sync (HMMA) ----------------
// C[B,N] = A[B,K] @ W[N,K]^T + bias; acc += Ah*Wh + Ah*Wl + Al*Wh (fp32 acc).
// CTA 128x128, BK=32, 256 threads, warp tile 64x32 (warps 2m x 4n).
// 2-stage cp.async pipeline, 80KB smem/CTA -> 2 CTAs/SM (16 warps/SM).
#define ARR_A   10240           // 128 * 80
#define ARR_W   10240           // 128 * 80
#define AW_OFF  (2 * ARR_A)
#define STAGE_B (2 * ARR_A + 2 * ARR_W)   // 40960
#define GSMEM   (2 * STAGE_B)             // 81920

template<int OUT_MODE>
__global__ void __launch_bounds__(256, 2)
mma_gemm_kernel(const __nv_bfloat16* __restrict__ Ah, const __nv_bfloat16* __restrict__ Al,
                const __nv_bfloat16* __restrict__ Wh, const __nv_bfloat16* __restrict__ Wl,
                const float* __restrict__ bias, float* __restrict__ Cf,
                __nv_bfloat16* __restrict__ Oh, __nv_bfloat16* __restrict__ Ol,
                int N, int K) {
    extern __shared__ char smem[];
    const uint32_t smem_u = smem_to_u32(smem);
    const int tid  = threadIdx.x;
    const int wid  = tid >> 5, lane = tid & 31;
    const int rowBase = blockIdx.y * 128;
    const int colBase = blockIdx.x * 128;
    const int warpM = wid & 1;      // 0..1  -> 64 rows
    const int warpN = wid >> 1;     // 0..3  -> 32 cols

    float acc[4][4][4];
    #pragma unroll
    for (int t = 0; t < 4; t++)
        #pragma unroll
        for (int f = 0; f < 4; f++)
            #pragma unroll
            for (int e = 0; e < 4; e++) acc[t][f][e] = 0.f;

    uint32_t aoff[4];
    #pragma unroll
    for (int t = 0; t < 4; t++)
        aoff[t] = (uint32_t)((warpM * 64 + t * 16 + (lane & 15)) * 80 + ((lane >> 4) << 4));
    uint32_t boff[2];
    #pragma unroll
    for (int g = 0; g < 2; g++) {
        int n = warpN * 32 + g * 16 + (lane & 7) + ((lane & 16) ? 8 : 0);
        boff[g] = (uint32_t)(AW_OFF + n * 80 + ((lane & 8) ? 16 : 0));
    }

    const int ktiles = K >> 5;

    auto fill = [&](int s, int kt) {
        const uint32_t stb = smem_u + s * STAGE_B;
        const int kOff = kt * 32;
        #pragma unroll
        for (int it = 0; it < 4; it++) {          // A chunks (Ah, Al)
            int idx = it * 256 + tid;             // 0..1023
            int arr = idx >> 9;
            int r   = (idx >> 2) & 127;
            int c   = idx & 3;
            const __nv_bfloat16* src =
                (arr ? Al : Ah) + (size_t)(rowBase + r) * K + kOff + c * 8;
            cp16(stb + arr * ARR_A + r * 80 + c * 16, src);
        }
        #pragma unroll
        for (int it = 0; it < 4; it++) {          // W chunks (Wh, Wl)
            int idx = it * 256 + tid;             // 0..1023
            int arr = idx >> 9;
            int r   = (idx >> 2) & 127;
            int c   = idx & 3;
            const __nv_bfloat16* src =
                (arr ? Wl : Wh) + (size_t)(colBase + r) * K + kOff + c * 8;
            cp16(stb + AW_OFF + arr * ARR_W + r * 80 + c * 16, src);
        }
        CP_COMMIT();
    };

    fill(0, 0);
    for (int kt = 0; kt < ktiles; kt++) {
        const int s = kt & 1;
        if (kt + 1 < ktiles) { fill(s ^ 1, kt + 1); CP_WAIT(1); }
        else                 { CP_WAIT(0); }
        __syncthreads();

        const uint32_t stb = smem_u + s * STAGE_B;
        #pragma unroll
        for (int kc = 0; kc < 2; kc++) {
            const uint32_t kb = kc * 32;
            uint32_t ah[4][4], al[4][4], bh[2][4], bl[2][4];
            #pragma unroll
            for (int t = 0; t < 4; t++) {
                LDMATRIX_X4(ah[t][0], ah[t][1], ah[t][2], ah[t][3], stb + aoff[t] + kb);
                LDMATRIX_X4(al[t][0], al[t][1], al[t][2], al[t][3], stb + aoff[t] + ARR_A + kb);
            }
            #pragma unroll
            for (int g = 0; g < 2; g++) {
                LDMATRIX_X4(bh[g][0], bh[g][1], bh[g][2], bh[g][3], stb + boff[g] + kb);
                LDMATRIX_X4(bl[g][0], bl[g][1], bl[g][2], bl[g][3], stb + boff[g] + ARR_W + kb);
            }
            // product-major: each pass touches distinct accumulators
            #pragma unroll
            for (int t = 0; t < 4; t++)
                #pragma unroll
                for (int g = 0; g < 2; g++) {
                    MMA_BF16(acc[t][2 * g],     ah[t], bh[g][0], bh[g][1]);
                    MMA_BF16(acc[t][2 * g + 1], ah[t], bh[g][2], bh[g][3]);
                }
            #pragma unroll
            for (int t = 0; t < 4; t++)
                #pragma unroll
                for (int g = 0; g < 2; g++) {
                    MMA_BF16(acc[t][2 * g],     ah[t], bl[g][0], bl[g][1]);
                    MMA_BF16(acc[t][2 * g + 1], ah[t], bl[g][2], bl[g][3]);
                }
            #pragma unroll
            for (int t = 0; t < 4; t++)
                #pragma unroll
                for (int g = 0; g < 2; g++) {
                    MMA_BF16(acc[t][2 * g],     al[t], bh[g][0], bh[g][1]);
                    MMA_BF16(acc[t][2 * g + 1], al[t], bh[g][2], bh[g][3]);
                }
        }
        __syncthreads();
    }

    // epilogue
    const int mBase = rowBase + warpM * 64;
    const int nBase = colBase + warpN * 32;
    #pragma unroll
    for (int t = 0; t < 4; t++) {
        #pragma unroll
        for (int f = 0; f < 4; f++) {
            const int col = nBase + f * 8 + (lane & 3) * 2;
            const int r0  = mBase + t * 16 + (lane >> 2);
            const float bv0 = __ldg(bias + col), bv1 = __ldg(bias + col + 1);
            float v00 = acc[t][f][0] + bv0, v01 = acc[t][f][1] + bv1;
            float v10 = acc[t][f][2] + bv0, v11 = acc[t][f][3] + bv1;
            if (OUT_MODE == 0) {
                *(float2*)(Cf + (size_t)r0 * N + col)       = make_float2(v00, v01);
                *(float2*)(Cf + (size_t)(r0 + 8) * N + col) = make_float2(v10, v11);
            } else {
                v00 = v00 >= 0.f ? v00 : 0.2f * v00;
                v01 = v01 >= 0.f ? v01 : 0.2f * v01;
                v10 = v10 >= 0.f ? v10 : 0.2f * v10;
                v11 = v11 >= 0.f ? v11 : 0.2f * v11;
                __nv_bfloat16 h0, l0, h1, l1;
                split2(v00, h0, l0); split2(v01, h1, l1);
                *(__nv_bfloat162*)(Oh + (size_t)r0 * N + col) = __halves2bfloat162(h0, h1);
                *(__nv_bfloat162*)(Ol + (size_t)r0 * N + col) = __halves2bfloat162(l0, l1);
                split2(v10, h0, l0); split2(v11, h1, l1);
                *(__nv_bfloat162*)(Oh + (size_t)(r0 + 8) * N + col) = __halves2bfloat162(h0, h1);
                *(__nv_bfloat162*)(Ol + (size_t)(r0 + 8) * N + col) = __halves2bfloat162(l0, l1);
            }
        }
    }
}

// ---------------- LayerNorm + lrelu -> split-bf16 ----------------
__device__ __forceinline__ float block_reduce_sum(float val, float* red) {
    const int lane = threadIdx.x & 31;
    const int w    = threadIdx.x >> 5;
    #pragma unroll
    for (int o = 16; o; o >>= 1) val += __shfl_xor_sync(0xffffffffu, val, o);
    if (lane == 0) red[w] = val;
    __syncthreads();
    float t = (lane < 8) ? red[lane] : 0.f;
    if (w == 0) {
        #pragma unroll
        for (int o = 4; o; o >>= 1) t += __shfl_xor_sync(0xffffffffu, t, o);
        if (lane == 0) red[0] = t;
    }
    __syncthreads();
    float r = red[0];
    __syncthreads();
    return r;
}

template<int NV4>
__global__ __launch_bounds__(256)
void ln_split_kernel(const float* __restrict__ X, const float* __restrict__ g,
                     const float* __restrict__ b, __nv_bfloat16* __restrict__ Oh,
                     __nv_bfloat16* __restrict__ Ol) {
    const int H = NV4 * 1024;
    const int tid = threadIdx.x;
    const float* row = X + (size_t)blockIdx.x * H;
    __shared__ float red[8];

    float4 v[NV4];
    float s = 0.f;
    #pragma unroll
    for (int q = 0; q < NV4; q++) {
        v[q] = *(const float4*)(row + (tid + 256 * q) * 4);
        s += v[q].x + v[q].y + v[q].z + v[q].w;
    }
    const float mean = block_reduce_sum(s, red) * (1.f / H);

    float ss = 0.f;
    #pragma unroll
    for (int q = 0; q < NV4; q++) {
        float dx;
        dx = v[q].x - mean; ss += dx * dx;
        dx = v[q].y - mean; ss += dx * dx;
        dx = v[q].z - mean; ss += dx * dx;
        dx = v[q].w - mean; ss += dx * dx;
    }
    const float var  = block_reduce_sum(ss, red) * (1.f / H);
    const float rstd = rsqrtf(var + 1e-5f);

    __nv_bfloat16* oh = Oh + (size_t)blockIdx.x * H;
    __nv_bfloat16* ol = Ol + (size_t)blockIdx.x * H;
    #pragma unroll
    for (int q = 0; q < NV4; q++) {
        const int col = (tid + 256 * q) * 4;
        const float4 g4 = *(const float4*)(g + col);
        const float4 b4 = *(const float4*)(b + col);
        float y0 = (v[q].x - mean) * rstd * g4.x + b4.x; y0 = y0 >= 0.f ? y0 : 0.2f * y0;
        float y1 = (v[q].y - mean) * rstd * g4.y + b4.y; y1 = y1 >= 0.f ? y1 : 0.2f * y1;
        float y2 = (v[q].z - mean) * rstd * g4.z + b4.z; y2 = y2 >= 0.f ? y2 : 0.2f * y2;
        float y3 = (v[q].w - mean) * rstd * g4.w + b4.w; y3 = y3 >= 0.f ? y3 : 0.2f * y3;
        __nv_bfloat16 h0, l0, h1, l1, h2, l2, h3, l3;
        split2(y0, h0, l0); split2(y1, h1, l1); split2(y2, h2, l2); split2(y3, h3, l3);
        *(__nv_bfloat162*)(oh + col)     = __halves2bfloat162(h0, h1);
        *(__nv_bfloat162*)(oh + col + 2) = __halves2bfloat162(h2, h3);
        *(__nv_bfloat162*)(ol + col)     = __halves2bfloat162(l0, l1);
        *(__nv_bfloat162*)(ol + col + 2) = __halves2bfloat162(l2, l3);
    }
}

// ---------------- reparam + context attention -> split-bf16 ----------------
__global__ __launch_bounds__(256)
void reparam_attn_kernel(const float* __restrict__ muv, const float* __restrict__ eps,
                         const float* __restrict__ ctx,
                         float* __restrict__ out_mu, float* __restrict__ out_lv,
                         __nv_bfloat16* __restrict__ Zh, __nv_bfloat16* __restrict__ Zl) {
    __shared__ float ctxs[M_][L_ + 1];
    __shared__ float zs[8][L_];
    __shared__ float attns[8][M_];

    const int tid = threadIdx.x;
    for (int i = tid; i < M_ * L_; i += 256)
        ctxs[i >> 8][i & 255] = ctx[i];
    __syncthreads();

    const int w    = tid >> 5;
    const int lane = tid & 31;
    const size_t row = (size_t)blockIdx.x * 8 + w;
    const float* mvrow = muv + row * 512;
    const float* eprow = eps + row * L_;

    #pragma unroll
    for (int i = 0; i < 8; i++) {
        const int j = lane + 32 * i;
        const float mu = mvrow[j], lv = mvrow[256 + j];
        out_mu[row * L_ + j] = mu;
        out_lv[row * L_ + j] = lv;
        zs[w][j] = mu + eprow[j] * expf(0.5f * lv);
    }
    __syncwarp();

    float s = 0.f;
    #pragma unroll 8
    for (int j = 0; j < L_; j++)
        s = fmaf(zs[w][j], ctxs[lane][j], s);

    float mx = s;
    #pragma unroll
    for (int o = 16; o; o >>= 1) mx = fmaxf(mx, __shfl_xor_sync(0xffffffffu, mx, o));
    float e = expf(s - mx);
    float tot = e;
    #pragma unroll
    for (int o = 16; o; o >>= 1) tot += __shfl_xor_sync(0xffffffffu, tot, o);
    attns[w][lane] = e / tot;
    __syncwarp();

    __nv_bfloat16* zh = Zh + row * L_;
    __nv_bfloat16* zl = Zl + row * L_;
    #pragma unroll
    for (int i = 0; i < 8; i++) {
        const int j = lane + 32 * i;
        float add = 0.f;
        #pragma unroll
        for (int m = 0; m < M_; m++)
            add = fmaf(attns[w][m], ctxs[m][j], add);
        float v = zs[w][j] + 0.1f * add;
        __nv_bfloat16 h, l;
        split2(v, h, l);
        zh[j] = h; zl[j] = l;
    }
}

// ---------------------------------------------------------------------------
extern "C" void kernel_launch(void* const* d_in, const int* in_sizes, int n_in,
                              void* d_out, int out_size) {
    (void)in_sizes; (void)n_in; (void)out_size;
    const float* x      = (const float*)d_in[0];
    const float* eps    = (const float*)d_in[1];
    const float* enc_w1 = (const float*)d_in[2];
    const float* enc_b1 = (const float*)d_in[3];
    const float* ln1_g  = (const float*)d_in[4];
    const float* ln1_b  = (const float*)d_in[5];
    const float* enc_w2 = (const float*)d_in[6];
    const float* enc_b2 = (const float*)d_in[7];
    const float* ln2_g  = (const float*)d_in[8];
    const float* ln2_b  = (const float*)d_in[9];
    const float* mu_w   = (const float*)d_in[10];
    const float* mu_b   = (const float*)d_in[11];
    const float* lv_w   = (const float*)d_in[12];
    const float* lv_b   = (const float*)d_in[13];
    const float* di_w   = (const float*)d_in[14];
    const float* di_b   = (const float*)d_in[15];
    const float* dec_w1 = (const float*)d_in[16];
    const float* dec_b1 = (const float*)d_in[17];
    const float* dln1_g = (const float*)d_in[18];
    const float* dln1_b = (const float*)d_in[19];
    const float* dec_w2 = (const float*)d_in[20];
    const float* dec_b2 = (const float*)d_in[21];
    const float* dln2_g = (const float*)d_in[22];
    const float* dln2_b = (const float*)d_in[23];
    const float* dec_w3 = (const float*)d_in[24];
    const float* dec_b3 = (const float*)d_in[25];
    const float* ctx    = (const float*)d_in[26];

    float* out     = (float*)d_out;
    float* out_rec = out;
    float* out_mu  = out + (size_t)B_ * D_;
    float* out_lv  = out_mu + (size_t)B_ * L_;

    __nv_bfloat16 *wh, *wl, *p1h, *p1l, *p2h, *p2l;
    float *f32buf, *bias512;
    cudaGetSymbolAddress((void**)&wh, g_wh);
    cudaGetSymbolAddress((void**)&wl, g_wl);
    cudaGetSymbolAddress((void**)&p1h, g_p1h);
    cudaGetSymbolAddress((void**)&p1l, g_p1l);
    cudaGetSymbolAddress((void**)&p2h, g_p2h);
    cudaGetSymbolAddress((void**)&p2l, g_p2l);
    cudaGetSymbolAddress((void**)&f32buf, g_f32);
    cudaGetSymbolAddress((void**)&bias512, g_bias512);

    cudaFuncSetAttribute(mma_gemm_kernel<0>, cudaFuncAttributeMaxDynamicSharedMemorySize, GSMEM);
    cudaFuncSetAttribute(mma_gemm_kernel<1>, cudaFuncAttributeMaxDynamicSharedMemorySize, GSMEM);

    const size_t o_e1 = 0,       o_e2 = 786432,  o_mu = 1835008, o_lv = 2097152;
    const size_t o_di = 2359296, o_d1 = 2621440, o_d2 = 3670016, o_d3 = 5767168;

    cudaMemcpyAsync(bias512,       mu_b, 256 * sizeof(float), cudaMemcpyDeviceToDevice);
    cudaMemcpyAsync(bias512 + 256, lv_b, 256 * sizeof(float), cudaMemcpyDeviceToDevice);

    const dim3 blk(256);
    auto splt = [&](const float* s, __nv_bfloat16* h, __nv_bfloat16* l, size_t n) {
        int n4 = (int)(n / 4);
        split_kernel<<<(n4 + 255) / 256, blk>>>(s, h, l, n4);
    };

    splt(x,      p1h,       p1l,       (size_t)B_ * D_);
    splt(enc_w1, wh + o_e1, wl + o_e1, (size_t)H_ * D_);
    splt(enc_w2, wh + o_e2, wl + o_e2, (size_t)H_ * H_);
    splt(mu_w,   wh + o_mu, wl + o_mu, (size_t)L_ * H_);
    splt(lv_w,   wh + o_lv, wl + o_lv, (size_t)L_ * H_);
    splt(di_w,   wh + o_di, wl + o_di, (size_t)H_ * L_);
    splt(dec_w1, wh + o_d1, wl + o_d1, (size_t)H_ * H_);
    splt(dec_w2, wh + o_d2, wl + o_d2, (size_t)2 * H_ * H_);
    splt(dec_w3, wh + o_d3, wl + o_d3, (size_t)D_ * 2 * H_);

    auto gemm = [&](int mode, const __nv_bfloat16* ah, const __nv_bfloat16* al,
                    size_t wo, const float* bias, float* cf,
                    __nv_bfloat16* oh, __nv_bfloat16* ol, int N, int K) {
        dim3 g(N / 128, B_ / 128);
        if (mode == 0)
            mma_gemm_kernel<0><<<g, blk, GSMEM>>>(ah, al, wh + wo, wl + wo, bias, cf, oh, ol, N, K);
        else
            mma_gemm_kernel<1><<<g, blk, GSMEM>>>(ah, al, wh + wo, wl + wo, bias, cf, oh, ol, N, K);
    };

    // encoder
    gemm(0, p1h, p1l, o_e1, enc_b1, f32buf, nullptr, nullptr, H_, D_);
    ln_split_kernel<1><<<B_, blk>>>(f32buf, ln1_g, ln1_b, p2h, p2l);
    gemm(0, p2h, p2l, o_e2, enc_b2, f32buf, nullptr, nullptr, H_, H_);
    ln_split_kernel<1><<<B_, blk>>>(f32buf, ln2_g, ln2_b, p1h, p1l);
    // merged mu|lv GEMM -> f32buf [B, 512]
    gemm(0, p1h, p1l, o_mu, bias512, f32buf, nullptr, nullptr, 512, H_);
    reparam_attn_kernel<<<B_ / 8, blk>>>(f32buf, eps, ctx, out_mu, out_lv, p2h, p2l);
    // decoder
    gemm(1, p2h, p2l, o_di, di_b, nullptr, p1h, p1l, H_, L_);
    gemm(0, p1h, p1l, o_d1, dec_b1, f32buf, nullptr, nullptr, H_, H_);
    ln_split_kernel<1><<<B_, blk>>>(f32buf, dln1_g, dln1_b, p2h, p2l);
    gemm(0, p2h, p2l, o_d2, dec_b2, f32buf, nullptr, nullptr, 2 * H_, H_);
    ln_split_kernel<2><<<B_, blk>>>(f32buf, dln2_g, dln2_b, p1h, p1l);
    gemm(0, p1h, p1l, o_d3, dec_b3, out_rec, nullptr, nullptr, D_, 2 * H_);
}

// round 13
// speedup vs baseline: 1.1230x; 1.0056x over previous
#include <cuda_runtime.h>
#include <cuda_bf16.h>
#include <cstdint>
#include <math.h>

#define B_  32768
#define D_  768
#define H_  1024
#define L_  256
#define M_  32

// ---------------- helpers ----------------
__device__ __forceinline__ uint32_t smem_to_u32(const void* p) {
    uint32_t a;
    asm("{ .reg .u64 t; cvta.to.shared.u64 t, %1; cvt.u32.u64 %0, t; }" : "=r"(a) : "l"(p));
    return a;
}
__device__ __forceinline__ void cp16(uint32_t dst, const void* src) {
    asm volatile("cp.async.cg.shared.global [%0], [%1], 16;\n" :: "r"(dst), "l"(src) : "memory");
}
#define CP_COMMIT()  asm volatile("cp.async.commit_group;\n" ::: "memory")
#define CP_WAIT(n)   asm volatile("cp.async.wait_group %0;\n" :: "n"(n) : "memory")
#define LDMATRIX_X4(r0, r1, r2, r3, addr) \
    asm volatile("ldmatrix.sync.aligned.m8n8.x4.shared.b16 {%0,%1,%2,%3}, [%4];" \
                 : "=r"(r0), "=r"(r1), "=r"(r2), "=r"(r3) : "r"(addr))
#define MMA_BF16(d, a, b0, b1) \
    asm volatile("mma.sync.aligned.m16n8k16.row.col.f32.bf16.bf16.f32 " \
                 "{%0,%1,%2,%3}, {%4,%5,%6,%7}, {%8,%9}, {%0,%1,%2,%3};" \
                 : "+f"((d)[0]), "+f"((d)[1]), "+f"((d)[2]), "+f"((d)[3]) \
                 : "r"((a)[0]), "r"((a)[1]), "r"((a)[2]), "r"((a)[3]), "r"(b0), "r"(b1))

// ---------------- scratch ----------------
#define WTOT 7340032
#define PMAX ((size_t)B_ * 2 * H_)
__device__ __nv_bfloat16 g_wh[WTOT], g_wl[WTOT];
__device__ __nv_bfloat16 g_p1h[PMAX], g_p1l[PMAX], g_p2h[PMAX], g_p2l[PMAX];
__device__ float g_f32[PMAX];
__device__ float g_bias512[512];

__device__ __forceinline__ void split2(float v, __nv_bfloat16& h, __nv_bfloat16& l) {
    h = __float2bfloat16(v);
    l = __float2bfloat16(v - __bfloat162float(h));
}

// ---------------- fp32 -> (hi,lo) bf16 split ----------------
__global__ __launch_bounds__(256)
void split_kernel(const float* __restrict__ src, __nv_bfloat16* __restrict__ hi,
                  __nv_bfloat16* __restrict__ lo, int n4) {
    int i = blockIdx.x * 256 + threadIdx.x;
    if (i >= n4) return;
    float4 v = ((const float4*)src)[i];
    __nv_bfloat16 h0, l0, h1, l1, h2, l2, h3, l3;
    split2(v.x, h0, l0); split2(v.y, h1, l1); split2(v.z, h2, l2); split2(v.w, h3, l3);
    ((__nv_bfloat162*)hi)[i * 2]     = __halves2bfloat162(h0, h1);
    ((__nv_bfloat162*)hi)[i * 2 + 1] = __halves2bfloat162(h2, h3);
    ((__nv_bfloat162*)lo)[i * 2]     = __halves2bfloat162(l0, l1);
    ((__nv_bfloat162*)lo)[i * 2 + 1] = __halves2bfloat162(l2, l3);
}

// ---------------- split-bf16 GEMM via mma.sync (HMMA) ----------------
// C[B,N] = A[B,K] @ W[N,K]^T + bias; acc += Ah*Wh + Ah*Wl + Al*Wh (fp32 acc).
// CTA 128x128, BK=32, 256 threads, warp tile 64x32 (warps 2m x 4n).
// 2-stage cp.async pipeline, single __syncthreads per ktile (fill issued
// after the sync, overlapping the MMA phase). 80KB smem -> 2 CTAs/SM.
#define ARR_A   10240           // 128 * 80
#define ARR_W   10240           // 128 * 80
#define AW_OFF  (2 * ARR_A)
#define STAGE_B (2 * ARR_A + 2 * ARR_W)   // 40960
#define GSMEM   (2 * STAGE_B)             // 81920

template<int OUT_MODE>
__global__ void __launch_bounds__(256, 2)
mma_gemm_kernel(const __nv_bfloat16* __restrict__ Ah, const __nv_bfloat16* __restrict__ Al,
                const __nv_bfloat16* __restrict__ Wh, const __nv_bfloat16* __restrict__ Wl,
                const float* __restrict__ bias, float* __restrict__ Cf,
                __nv_bfloat16* __restrict__ Oh, __nv_bfloat16* __restrict__ Ol,
                int N, int K) {
    extern __shared__ char smem[];
    const uint32_t smem_u = smem_to_u32(smem);
    const int tid  = threadIdx.x;
    const int wid  = tid >> 5, lane = tid & 31;
    const int rowBase = blockIdx.y * 128;
    const int colBase = blockIdx.x * 128;
    const int warpM = wid & 1;      // 0..1  -> 64 rows
    const int warpN = wid >> 1;     // 0..3  -> 32 cols

    float acc[4][4][4];
    #pragma unroll
    for (int t = 0; t < 4; t++)
        #pragma unroll
        for (int f = 0; f < 4; f++)
            #pragma unroll
            for (int e = 0; e < 4; e++) acc[t][f][e] = 0.f;

    uint32_t aoff[4];
    #pragma unroll
    for (int t = 0; t < 4; t++)
        aoff[t] = (uint32_t)((warpM * 64 + t * 16 + (lane & 15)) * 80 + ((lane >> 4) << 4));
    uint32_t boff[2];
    #pragma unroll
    for (int g = 0; g < 2; g++) {
        int n = warpN * 32 + g * 16 + (lane & 7) + ((lane & 16) ? 8 : 0);
        boff[g] = (uint32_t)(AW_OFF + n * 80 + ((lane & 8) ? 16 : 0));
    }

    const int ktiles = K >> 5;

    // per-thread fill addressing, hoisted: thread covers 8 rows total
    // (4 A-array rows, 4 W-array rows), fixed (r, c) per chunk.
    const int f_r = (tid >> 2) & 127;      // row 0..127
    const int f_c = tid & 3;               // 16B chunk 0..3
    const int f_arr = tid >> 9;            // always 0 for 256 thr; use loop
    (void)f_arr;

    auto fill = [&](int s, int kt) {
        const uint32_t stb = smem_u + s * STAGE_B;
        const int kOff = kt * 32 + f_c * 8;
        const uint32_t sOff = f_r * 80 + f_c * 16;
        // A hi, A lo, W hi, W lo : one 16B chunk each per sub-iteration
        #pragma unroll
        for (int half = 0; half < 2; half++) {
            int r = f_r + half * 0;        // 256 threads cover 64 rows per pass? no:
            (void)r;
        }
        // 256 threads * 4 chunks-of-16B rows mapping: idx = it*256+tid covers
        // 1024 chunks per array pair as before.
        #pragma unroll
        for (int it = 0; it < 4; it++) {
            int idx = it * 256 + tid;
            int arr = idx >> 9;
            int r   = (idx >> 2) & 127;
            int c   = idx & 3;
            const __nv_bfloat16* src =
                (arr ? Al : Ah) + (size_t)(rowBase + r) * K + kt * 32 + c * 8;
            cp16(stb + arr * ARR_A + r * 80 + c * 16, src);
        }
        #pragma unroll
        for (int it = 0; it < 4; it++) {
            int idx = it * 256 + tid;
            int arr = idx >> 9;
            int r   = (idx >> 2) & 127;
            int c   = idx & 3;
            const __nv_bfloat16* src =
                (arr ? Wl : Wh) + (size_t)(colBase + r) * K + kt * 32 + c * 8;
            cp16(stb + AW_OFF + arr * ARR_W + r * 80 + c * 16, src);
        }
        CP_COMMIT();
        (void)kOff; (void)sOff;
    };

    fill(0, 0);
    for (int kt = 0; kt < ktiles; kt++) {
        const int s = kt & 1;
        CP_WAIT(0);
        __syncthreads();                       // single barrier per ktile
        if (kt + 1 < ktiles) fill(s ^ 1, kt + 1);   // overlaps MMAs below

        const uint32_t stb = smem_u + s * STAGE_B;
        #pragma unroll
        for (int kc = 0; kc < 2; kc++) {
            const uint32_t kb = kc * 32;
            uint32_t ah[4][4], al[4][4], bh[2][4], bl[2][4];
            #pragma unroll
            for (int t = 0; t < 4; t++) {
                LDMATRIX_X4(ah[t][0], ah[t][1], ah[t][2], ah[t][3], stb + aoff[t] + kb);
                LDMATRIX_X4(al[t][0], al[t][1], al[t][2], al[t][3], stb + aoff[t] + ARR_A + kb);
            }
            #pragma unroll
            for (int g = 0; g < 2; g++) {
                LDMATRIX_X4(bh[g][0], bh[g][1], bh[g][2], bh[g][3], stb + boff[g] + kb);
                LDMATRIX_X4(bl[g][0], bl[g][1], bl[g][2], bl[g][3], stb + boff[g] + ARR_W + kb);
            }
            #pragma unroll
            for (int t = 0; t < 4; t++)
                #pragma unroll
                for (int g = 0; g < 2; g++) {
                    MMA_BF16(acc[t][2 * g],     ah[t], bh[g][0], bh[g][1]);
                    MMA_BF16(acc[t][2 * g + 1], ah[t], bh[g][2], bh[g][3]);
                }
            #pragma unroll
            for (int t = 0; t < 4; t++)
                #pragma unroll
                for (int g = 0; g < 2; g++) {
                    MMA_BF16(acc[t][2 * g],     ah[t], bl[g][0], bl[g][1]);
                    MMA_BF16(acc[t][2 * g + 1], ah[t], bl[g][2], bl[g][3]);
                }
            #pragma unroll
            for (int t = 0; t < 4; t++)
                #pragma unroll
                for (int g = 0; g < 2; g++) {
                    MMA_BF16(acc[t][2 * g],     al[t], bh[g][0], bh[g][1]);
                    MMA_BF16(acc[t][2 * g + 1], al[t], bh[g][2], bh[g][3]);
                }
        }
    }

    // epilogue (no final barrier needed: only registers from here)
    const int mBase = rowBase + warpM * 64;
    const int nBase = colBase + warpN * 32;
    #pragma unroll
    for (int t = 0; t < 4; t++) {
        #pragma unroll
        for (int f = 0; f < 4; f++) {
            const int col = nBase + f * 8 + (lane & 3) * 2;
            const int r0  = mBase + t * 16 + (lane >> 2);
            const float bv0 = __ldg(bias + col), bv1 = __ldg(bias + col + 1);
            float v00 = acc[t][f][0] + bv0, v01 = acc[t][f][1] + bv1;
            float v10 = acc[t][f][2] + bv0, v11 = acc[t][f][3] + bv1;
            if (OUT_MODE == 0) {
                *(float2*)(Cf + (size_t)r0 * N + col)       = make_float2(v00, v01);
                *(float2*)(Cf + (size_t)(r0 + 8) * N + col) = make_float2(v10, v11);
            } else {
                v00 = v00 >= 0.f ? v00 : 0.2f * v00;
                v01 = v01 >= 0.f ? v01 : 0.2f * v01;
                v10 = v10 >= 0.f ? v10 : 0.2f * v10;
                v11 = v11 >= 0.f ? v11 : 0.2f * v11;
                __nv_bfloat16 h0, l0, h1, l1;
                split2(v00, h0, l0); split2(v01, h1, l1);
                *(__nv_bfloat162*)(Oh + (size_t)r0 * N + col) = __halves2bfloat162(h0, h1);
                *(__nv_bfloat162*)(Ol + (size_t)r0 * N + col) = __halves2bfloat162(l0, l1);
                split2(v10, h0, l0); split2(v11, h1, l1);
                *(__nv_bfloat162*)(Oh + (size_t)(r0 + 8) * N + col) = __halves2bfloat162(h0, h1);
                *(__nv_bfloat162*)(Ol + (size_t)(r0 + 8) * N + col) = __halves2bfloat162(l0, l1);
            }
        }
    }
}

// ---------------- LayerNorm + lrelu -> split-bf16 ----------------
__device__ __forceinline__ float block_reduce_sum(float val, float* red) {
    const int lane = threadIdx.x & 31;
    const int w    = threadIdx.x >> 5;
    #pragma unroll
    for (int o = 16; o; o >>= 1) val += __shfl_xor_sync(0xffffffffu, val, o);
    if (lane == 0) red[w] = val;
    __syncthreads();
    float t = (lane < 8) ? red[lane] : 0.f;
    if (w == 0) {
        #pragma unroll
        for (int o = 4; o; o >>= 1) t += __shfl_xor_sync(0xffffffffu, t, o);
        if (lane == 0) red[0] = t;
    }
    __syncthreads();
    float r = red[0];
    __syncthreads();
    return r;
}

template<int NV4>
__global__ __launch_bounds__(256)
void ln_split_kernel(const float* __restrict__ X, const float* __restrict__ g,
                     const float* __restrict__ b, __nv_bfloat16* __restrict__ Oh,
                     __nv_bfloat16* __restrict__ Ol) {
    const int H = NV4 * 1024;
    const int tid = threadIdx.x;
    const float* row = X + (size_t)blockIdx.x * H;
    __shared__ float red[8];

    float4 v[NV4];
    float s = 0.f;
    #pragma unroll
    for (int q = 0; q < NV4; q++) {
        v[q] = *(const float4*)(row + (tid + 256 * q) * 4);
        s += v[q].x + v[q].y + v[q].z + v[q].w;
    }
    const float mean = block_reduce_sum(s, red) * (1.f / H);

    float ss = 0.f;
    #pragma unroll
    for (int q = 0; q < NV4; q++) {
        float dx;
        dx = v[q].x - mean; ss += dx * dx;
        dx = v[q].y - mean; ss += dx * dx;
        dx = v[q].z - mean; ss += dx * dx;
        dx = v[q].w - mean; ss += dx * dx;
    }
    const float var  = block_reduce_sum(ss, red) * (1.f / H);
    const float rstd = rsqrtf(var + 1e-5f);

    __nv_bfloat16* oh = Oh + (size_t)blockIdx.x * H;
    __nv_bfloat16* ol = Ol + (size_t)blockIdx.x * H;
    #pragma unroll
    for (int q = 0; q < NV4; q++) {
        const int col = (tid + 256 * q) * 4;
        const float4 g4 = *(const float4*)(g + col);
        const float4 b4 = *(const float4*)(b + col);
        float y0 = (v[q].x - mean) * rstd * g4.x + b4.x; y0 = y0 >= 0.f ? y0 : 0.2f * y0;
        float y1 = (v[q].y - mean) * rstd * g4.y + b4.y; y1 = y1 >= 0.f ? y1 : 0.2f * y1;
        float y2 = (v[q].z - mean) * rstd * g4.z + b4.z; y2 = y2 >= 0.f ? y2 : 0.2f * y2;
        float y3 = (v[q].w - mean) * rstd * g4.w + b4.w; y3 = y3 >= 0.f ? y3 : 0.2f * y3;
        __nv_bfloat16 h0, l0, h1, l1, h2, l2, h3, l3;
        split2(y0, h0, l0); split2(y1, h1, l1); split2(y2, h2, l2); split2(y3, h3, l3);
        *(__nv_bfloat162*)(oh + col)     = __halves2bfloat162(h0, h1);
        *(__nv_bfloat162*)(oh + col + 2) = __halves2bfloat162(h2, h3);
        *(__nv_bfloat162*)(ol + col)     = __halves2bfloat162(l0, l1);
        *(__nv_bfloat162*)(ol + col + 2) = __halves2bfloat162(l2, l3);
    }
}

// ---------------- reparam + context attention -> split-bf16 ----------------
__global__ __launch_bounds__(256)
void reparam_attn_kernel(const float* __restrict__ muv, const float* __restrict__ eps,
                         const float* __restrict__ ctx,
                         float* __restrict__ out_mu, float* __restrict__ out_lv,
                         __nv_bfloat16* __restrict__ Zh, __nv_bfloat16* __restrict__ Zl) {
    __shared__ float ctxs[M_][L_ + 1];
    __shared__ float zs[8][L_];
    __shared__ float attns[8][M_];

    const int tid = threadIdx.x;
    for (int i = tid; i < M_ * L_; i += 256)
        ctxs[i >> 8][i & 255] = ctx[i];
    __syncthreads();

    const int w    = tid >> 5;
    const int lane = tid & 31;
    const size_t row = (size_t)blockIdx.x * 8 + w;
    const float* mvrow = muv + row * 512;
    const float* eprow = eps + row * L_;

    #pragma unroll
    for (int i = 0; i < 8; i++) {
        const int j = lane + 32 * i;
        const float mu = mvrow[j], lv = mvrow[256 + j];
        out_mu[row * L_ + j] = mu;
        out_lv[row * L_ + j] = lv;
        zs[w][j] = mu + eprow[j] * expf(0.5f * lv);
    }
    __syncwarp();

    float s = 0.f;
    #pragma unroll 8
    for (int j = 0; j < L_; j++)
        s = fmaf(zs[w][j], ctxs[lane][j], s);

    float mx = s;
    #pragma unroll
    for (int o = 16; o; o >>= 1) mx = fmaxf(mx, __shfl_xor_sync(0xffffffffu, mx, o));
    float e = expf(s - mx);
    float tot = e;
    #pragma unroll
    for (int o = 16; o; o >>= 1) tot += __shfl_xor_sync(0xffffffffu, tot, o);
    attns[w][lane] = e / tot;
    __syncwarp();

    __nv_bfloat16* zh = Zh + row * L_;
    __nv_bfloat16* zl = Zl + row * L_;
    #pragma unroll
    for (int i = 0; i < 8; i++) {
        const int j = lane + 32 * i;
        float add = 0.f;
        #pragma unroll
        for (int m = 0; m < M_; m++)
            add = fmaf(attns[w][m], ctxs[m][j], add);
        float v = zs[w][j] + 0.1f * add;
        __nv_bfloat16 h, l;
        split2(v, h, l);
        zh[j] = h; zl[j] = l;
    }
}

// ---------------------------------------------------------------------------
extern "C" void kernel_launch(void* const* d_in, const int* in_sizes, int n_in,
                              void* d_out, int out_size) {
    (void)in_sizes; (void)n_in; (void)out_size;
    const float* x      = (const float*)d_in[0];
    const float* eps    = (const float*)d_in[1];
    const float* enc_w1 = (const float*)d_in[2];
    const float* enc_b1 = (const float*)d_in[3];
    const float* ln1_g  = (const float*)d_in[4];
    const float* ln1_b  = (const float*)d_in[5];
    const float* enc_w2 = (const float*)d_in[6];
    const float* enc_b2 = (const float*)d_in[7];
    const float* ln2_g  = (const float*)d_in[8];
    const float* ln2_b  = (const float*)d_in[9];
    const float* mu_w   = (const float*)d_in[10];
    const float* mu_b   = (const float*)d_in[11];
    const float* lv_w   = (const float*)d_in[12];
    const float* lv_b   = (const float*)d_in[13];
    const float* di_w   = (const float*)d_in[14];
    const float* di_b   = (const float*)d_in[15];
    const float* dec_w1 = (const float*)d_in[16];
    const float* dec_b1 = (const float*)d_in[17];
    const float* dln1_g = (const float*)d_in[18];
    const float* dln1_b = (const float*)d_in[19];
    const float* dec_w2 = (const float*)d_in[20];
    const float* dec_b2 = (const float*)d_in[21];
    const float* dln2_g = (const float*)d_in[22];
    const float* dln2_b = (const float*)d_in[23];
    const float* dec_w3 = (const float*)d_in[24];
    const float* dec_b3 = (const float*)d_in[25];
    const float* ctx    = (const float*)d_in[26];

    float* out     = (float*)d_out;
    float* out_rec = out;
    float* out_mu  = out + (size_t)B_ * D_;
    float* out_lv  = out_mu + (size_t)B_ * L_;

    __nv_bfloat16 *wh, *wl, *p1h, *p1l, *p2h, *p2l;
    float *f32buf, *bias512;
    cudaGetSymbolAddress((void**)&wh, g_wh);
    cudaGetSymbolAddress((void**)&wl, g_wl);
    cudaGetSymbolAddress((void**)&p1h, g_p1h);
    cudaGetSymbolAddress((void**)&p1l, g_p1l);
    cudaGetSymbolAddress((void**)&p2h, g_p2h);
    cudaGetSymbolAddress((void**)&p2l, g_p2l);
    cudaGetSymbolAddress((void**)&f32buf, g_f32);
    cudaGetSymbolAddress((void**)&bias512, g_bias512);

    cudaFuncSetAttribute(mma_gemm_kernel<0>, cudaFuncAttributeMaxDynamicSharedMemorySize, GSMEM);
    cudaFuncSetAttribute(mma_gemm_kernel<1>, cudaFuncAttributeMaxDynamicSharedMemorySize, GSMEM);

    const size_t o_e1 = 0,       o_e2 = 786432,  o_mu = 1835008, o_lv = 2097152;
    const size_t o_di = 2359296, o_d1 = 2621440, o_d2 = 3670016, o_d3 = 5767168;

    cudaMemcpyAsync(bias512,       mu_b, 256 * sizeof(float), cudaMemcpyDeviceToDevice);
    cudaMemcpyAsync(bias512 + 256, lv_b, 256 * sizeof(float), cudaMemcpyDeviceToDevice);

    const dim3 blk(256);
    auto splt = [&](const float* s, __nv_bfloat16* h, __nv_bfloat16* l, size_t n) {
        int n4 = (int)(n / 4);
        split_kernel<<<(n4 + 255) / 256, blk>>>(s, h, l, n4);
    };

    splt(x,      p1h,       p1l,       (size_t)B_ * D_);
    splt(enc_w1, wh + o_e1, wl + o_e1, (size_t)H_ * D_);
    splt(enc_w2, wh + o_e2, wl + o_e2, (size_t)H_ * H_);
    splt(mu_w,   wh + o_mu, wl + o_mu, (size_t)L_ * H_);
    splt(lv_w,   wh + o_lv, wl + o_lv, (size_t)L_ * H_);
    splt(di_w,   wh + o_di, wl + o_di, (size_t)H_ * L_);
    splt(dec_w1, wh + o_d1, wl + o_d1, (size_t)H_ * H_);
    splt(dec_w2, wh + o_d2, wl + o_d2, (size_t)2 * H_ * H_);
    splt(dec_w3, wh + o_d3, wl + o_d3, (size_t)D_ * 2 * H_);

    auto gemm = [&](int mode, const __nv_bfloat16* ah, const __nv_bfloat16* al,
                    size_t wo, const float* bias, float* cf,
                    __nv_bfloat16* oh, __nv_bfloat16* ol, int N, int K) {
        dim3 g(N / 128, B_ / 128);
        if (mode == 0)
            mma_gemm_kernel<0><<<g, blk, GSMEM>>>(ah, al, wh + wo, wl + wo, bias, cf, oh, ol, N, K);
        else
            mma_gemm_kernel<1><<<g, blk, GSMEM>>>(ah, al, wh + wo, wl + wo, bias, cf, oh, ol, N, K);
    };

    // encoder
    gemm(0, p1h, p1l, o_e1, enc_b1, f32buf, nullptr, nullptr, H_, D_);
    ln_split_kernel<1><<<B_, blk>>>(f32buf, ln1_g, ln1_b, p2h, p2l);
    gemm(0, p2h, p2l, o_e2, enc_b2, f32buf, nullptr, nullptr, H_, H_);
    ln_split_kernel<1><<<B_, blk>>>(f32buf, ln2_g, ln2_b, p1h, p1l);
    // merged mu|lv GEMM -> f32buf [B, 512]
    gemm(0, p1h, p1l, o_mu, bias512, f32buf, nullptr, nullptr, 512, H_);
    reparam_attn_kernel<<<B_ / 8, blk>>>(f32buf, eps, ctx, out_mu, out_lv, p2h, p2l);
    // decoder
    gemm(1, p2h, p2l, o_di, di_b, nullptr, p1h, p1l, H_, L_);
    gemm(0, p1h, p1l, o_d1, dec_b1, f32buf, nullptr, nullptr, H_, H_);
    ln_split_kernel<1><<<B_, blk>>>(f32buf, dln1_g, dln1_b, p2h, p2l);
    gemm(0, p2h, p2l, o_d2, dec_b2, f32buf, nullptr, nullptr, 2 * H_, H_);
    ln_split_kernel<2><<<B_, blk>>>(f32buf, dln2_g, dln2_b, p1h, p1l);
    gemm(0, p1h, p1l, o_d3, dec_b3, out_rec, nullptr, nullptr, D_, 2 * H_);
}